// round 7
// baseline (speedup 1.0000x reference)
#include <cuda_runtime.h>
#include <math.h>
#include <stdint.h>

#define B_  2
#define S_  2048
#define D_  768
#define H_  12
#define HD_ 64
#define LOG2E 1.44269504f

// Q/K/V scratch in [B,H,S,hd] layout
__device__ float g_q[B_*H_*S_*HD_];
__device__ float g_k[B_*H_*S_*HD_];
__device__ float g_v[B_*H_*S_*HD_];

// ---------------------------------------------------------------------------
// helpers
// ---------------------------------------------------------------------------
__device__ __forceinline__ uint32_t f2tf32(float x) {
    uint32_t r;
    asm("cvt.rna.tf32.f32 %0, %1;" : "=r"(r) : "f"(x));
    return r;
}
__device__ __forceinline__ uint32_t fbits(float x) { return __float_as_uint(x); }

__device__ __forceinline__ float ex2(float x) {
    float r;
    asm("ex2.approx.f32 %0, %1;" : "=f"(r) : "f"(x));
    return r;
}

__device__ __forceinline__ void mma_tf32(float (&d)[4], const uint32_t (&a)[4],
                                         const uint32_t (&b)[2], const float (&c)[4]) {
    asm volatile(
        "mma.sync.aligned.m16n8k8.row.col.f32.tf32.tf32.f32 "
        "{%0,%1,%2,%3}, {%4,%5,%6,%7}, {%8,%9}, {%10,%11,%12,%13};\n"
        : "=f"(d[0]), "=f"(d[1]), "=f"(d[2]), "=f"(d[3])
        : "r"(a[0]), "r"(a[1]), "r"(a[2]), "r"(a[3]),
          "r"(b[0]), "r"(b[1]),
          "f"(c[0]), "f"(c[1]), "f"(c[2]), "f"(c[3]));
}

// Route a C-fragment column pair (pa=col 2t, pb=col 2t+1 of an 8-col tile)
// into A-fragment columns t and t+4 of the same 8-col k-chunk.
__device__ __forceinline__ void pfrag(float pa, float pb, int lane, float& x, float& y) {
    const int t = lane & 3;
    const int base = lane & ~3;
    const int s1 = base | (t >> 1);
    const int s2 = base | ((t >> 1) + 2);
    float v0 = __shfl_sync(0xffffffffu, pa, s1);
    float v1 = __shfl_sync(0xffffffffu, pb, s1);
    float w0 = __shfl_sync(0xffffffffu, pa, s2);
    float w1 = __shfl_sync(0xffffffffu, pb, s2);
    x = (t & 1) ? v1 : v0;
    y = (t & 1) ? w1 : w0;
}

// ---------------------------------------------------------------------------
// QKV projection GEMM (tf32 mma.sync) — unchanged (passing, ~96us)
// ---------------------------------------------------------------------------
__global__ __launch_bounds__(256, 2)
void qkv_mma_kernel(const float* __restrict__ A,
                    const float* __restrict__ Wq, const float* __restrict__ bq,
                    const float* __restrict__ Wk, const float* __restrict__ bk,
                    const float* __restrict__ Wv, const float* __restrict__ bv)
{
    const float* W; const float* bias; float* out;
    switch (blockIdx.z) {
        case 0:  W = Wq; bias = bq; out = g_q; break;
        case 1:  W = Wk; bias = bk; out = g_k; break;
        default: W = Wv; bias = bv; out = g_v; break;
    }

    __shared__ float As[128][36];
    __shared__ float Bs[32][72];

    const int tid  = threadIdx.x;
    const int w    = tid >> 5;
    const int lane = tid & 31;
    const int g    = lane >> 2;
    const int t    = lane & 3;
    const int wm   = w & 3;
    const int wn   = w >> 2;
    const int rowBase = blockIdx.y * 128;
    const int h       = blockIdx.x;
    const int colBase = h * 64;

    float acc[2][4][4];
    #pragma unroll
    for (int mt = 0; mt < 2; mt++)
        #pragma unroll
        for (int nt = 0; nt < 4; nt++)
            #pragma unroll
            for (int i = 0; i < 4; i++) acc[mt][nt][i] = 0.f;

    const int ar = tid >> 3, ac = (tid & 7) * 4;
    const int br = tid >> 4, bc = (tid & 15) * 4;

    for (int k0 = 0; k0 < D_; k0 += 32) {
        __syncthreads();
        #pragma unroll
        for (int p = 0; p < 4; p++) {
            float4 v = *(const float4*)&A[(size_t)(rowBase + ar + p*32) * D_ + k0 + ac];
            float* d = &As[ar + p*32][ac];
            d[0] = __uint_as_float(f2tf32(v.x));
            d[1] = __uint_as_float(f2tf32(v.y));
            d[2] = __uint_as_float(f2tf32(v.z));
            d[3] = __uint_as_float(f2tf32(v.w));
        }
        #pragma unroll
        for (int p = 0; p < 2; p++) {
            float4 v = *(const float4*)&W[(size_t)(k0 + br + p*16) * D_ + colBase + bc];
            float* d = &Bs[br + p*16][bc];
            d[0] = __uint_as_float(f2tf32(v.x));
            d[1] = __uint_as_float(f2tf32(v.y));
            d[2] = __uint_as_float(f2tf32(v.z));
            d[3] = __uint_as_float(f2tf32(v.w));
        }
        __syncthreads();

        #pragma unroll
        for (int kc = 0; kc < 4; kc++) {
            uint32_t af[2][4];
            #pragma unroll
            for (int mt = 0; mt < 2; mt++) {
                const int r = wm*32 + mt*16;
                af[mt][0] = fbits(As[r + g    ][kc*8 + t    ]);
                af[mt][1] = fbits(As[r + g + 8][kc*8 + t    ]);
                af[mt][2] = fbits(As[r + g    ][kc*8 + t + 4]);
                af[mt][3] = fbits(As[r + g + 8][kc*8 + t + 4]);
            }
            #pragma unroll
            for (int nt = 0; nt < 4; nt++) {
                uint32_t bf[2];
                bf[0] = fbits(Bs[kc*8 + t    ][wn*32 + nt*8 + g]);
                bf[1] = fbits(Bs[kc*8 + t + 4][wn*32 + nt*8 + g]);
                mma_tf32(acc[0][nt], af[0], bf, acc[0][nt]);
                mma_tf32(acc[1][nt], af[1], bf, acc[1][nt]);
            }
        }
    }

    #pragma unroll
    for (int mt = 0; mt < 2; mt++) {
        #pragma unroll
        for (int half = 0; half < 2; half++) {
            const int row = rowBase + wm*32 + mt*16 + g + half*8;
            const int b   = row >> 11;
            const int s   = row & (S_ - 1);
            float* orow = out + ((size_t)(b*H_ + h) * S_ + s) * HD_;
            #pragma unroll
            for (int nt = 0; nt < 4; nt++) {
                const int d = wn*32 + nt*8 + 2*t;
                float2 v;
                v.x = acc[mt][nt][half*2 + 0] + bias[colBase + d];
                v.y = acc[mt][nt][half*2 + 1] + bias[colBase + d + 1];
                *(float2*)&orow[d] = v;
            }
        }
    }
}

// ---------------------------------------------------------------------------
// Flash attention (tf32 mma.sync), occupancy-optimized:
// block = 128 (4 warps), 64 queries/CTA (warp owns 16), 3 CTAs/SM.
// K stored [key][d-interleaved], V stored transposed [d][key-interleaved]
// so every B-fragment pair is one LDS.64.
// Interleave within each 8-col chunk: c -> 2*(c&3) + ((c&4)>>2)
// grid = (S/64 = 32, B*H = 24)
// ---------------------------------------------------------------------------
__global__ __launch_bounds__(128, 3)
void attn_mma_kernel(const float* __restrict__ mask, float* __restrict__ out)
{
    __shared__ float Ks[64][72];   // [key][perm(d)]
    __shared__ float Vt[64][72];   // [d][perm(key)]
    __shared__ float Ms[64];

    const int tid  = threadIdx.x;
    const int w    = tid >> 5;
    const int lane = tid & 31;
    const int g    = lane >> 2;
    const int t    = lane & 3;

    const int bh = blockIdx.y;
    const int b  = bh / H_;
    const int h  = bh % H_;
    const int qBase = blockIdx.x * 64 + w * 16;

    const float* Qg = g_q + (size_t)bh * S_ * HD_;
    const float* Kg = g_k + (size_t)bh * S_ * HD_;
    const float* Vg = g_v + (size_t)bh * S_ * HD_;
    const float* mrow = mask + (size_t)b * S_;

    const float qscale = 0.125f * LOG2E;

    // Q fragments (reused across all key tiles)
    uint32_t qf[8][4];
    {
        const float* q0 = Qg + (size_t)(qBase + g)     * HD_;
        const float* q1 = Qg + (size_t)(qBase + g + 8) * HD_;
        #pragma unroll
        for (int kc = 0; kc < 8; kc++) {
            qf[kc][0] = f2tf32(q0[8*kc + t    ] * qscale);
            qf[kc][1] = f2tf32(q1[8*kc + t    ] * qscale);
            qf[kc][2] = f2tf32(q0[8*kc + t + 4] * qscale);
            qf[kc][3] = f2tf32(q1[8*kc + t + 4] * qscale);
        }
    }

    float o[8][4];
    #pragma unroll
    for (int dt = 0; dt < 8; dt++)
        #pragma unroll
        for (int i = 0; i < 4; i++) o[dt][i] = 0.f;

    float m0 = -INFINITY, m1 = -INFINITY, l0 = 0.f, l1 = 0.f;

    // loader mapping: pair of threads per row, fully coalesced 32B per pair
    const int lkey = tid >> 1;    // 0..63
    const int llq  = tid & 1;

    for (int t0 = 0; t0 < S_; t0 += 64) {
        __syncthreads();
        {
            const float* ksrc = Kg + (size_t)(t0 + lkey) * HD_;
            const float* vsrc = Vg + (size_t)(t0 + lkey) * HD_;
            const int vcol = (lkey & ~7) + 2*(lkey & 3) + ((lkey & 4) >> 2);
            #pragma unroll
            for (int i = 0; i < 8; i++) {
                const int d0 = (2*i + llq) * 4;
                const int cb = (d0 & ~7) + ((d0 >> 2) & 1);
                float4 kv = *(const float4*)(ksrc + d0);
                Ks[lkey][cb + 0] = __uint_as_float(f2tf32(kv.x));
                Ks[lkey][cb + 2] = __uint_as_float(f2tf32(kv.y));
                Ks[lkey][cb + 4] = __uint_as_float(f2tf32(kv.z));
                Ks[lkey][cb + 6] = __uint_as_float(f2tf32(kv.w));
                float4 vv = *(const float4*)(vsrc + d0);
                Vt[d0 + 0][vcol] = __uint_as_float(f2tf32(vv.x));
                Vt[d0 + 1][vcol] = __uint_as_float(f2tf32(vv.y));
                Vt[d0 + 2][vcol] = __uint_as_float(f2tf32(vv.z));
                Vt[d0 + 3][vcol] = __uint_as_float(f2tf32(vv.w));
            }
            if (tid < 64) Ms[tid] = mrow[t0 + tid] * LOG2E;
        }
        __syncthreads();

        // ---- S = (Q*scale) @ K^T + mask (log2 domain) ----
        float s[8][4];
        #pragma unroll
        for (int nt = 0; nt < 8; nt++) {
            #pragma unroll
            for (int i = 0; i < 4; i++) s[nt][i] = 0.f;
            #pragma unroll
            for (int kc = 0; kc < 8; kc++) {
                float2 kk = *(const float2*)&Ks[nt*8 + g][kc*8 + 2*t];
                uint32_t bf[2];
                bf[0] = fbits(kk.x);
                bf[1] = fbits(kk.y);
                mma_tf32(s[nt], qf[kc], bf, s[nt]);
            }
            const float mk0 = Ms[nt*8 + 2*t];
            const float mk1 = Ms[nt*8 + 2*t + 1];
            s[nt][0] += mk0;  s[nt][1] += mk1;
            s[nt][2] += mk0;  s[nt][3] += mk1;
        }

        // ---- online softmax ----
        float mx0 = -INFINITY, mx1 = -INFINITY;
        #pragma unroll
        for (int nt = 0; nt < 8; nt++) {
            mx0 = fmaxf(mx0, fmaxf(s[nt][0], s[nt][1]));
            mx1 = fmaxf(mx1, fmaxf(s[nt][2], s[nt][3]));
        }
        mx0 = fmaxf(mx0, __shfl_xor_sync(0xffffffffu, mx0, 1));
        mx0 = fmaxf(mx0, __shfl_xor_sync(0xffffffffu, mx0, 2));
        mx1 = fmaxf(mx1, __shfl_xor_sync(0xffffffffu, mx1, 1));
        mx1 = fmaxf(mx1, __shfl_xor_sync(0xffffffffu, mx1, 2));

        const float nm0 = fmaxf(m0, mx0);
        const float nm1 = fmaxf(m1, mx1);
        const float c0 = ex2(m0 - nm0);
        const float c1 = ex2(m1 - nm1);
        m0 = nm0; m1 = nm1;

        float sum0 = 0.f, sum1 = 0.f;
        #pragma unroll
        for (int nt = 0; nt < 8; nt++) {
            s[nt][0] = ex2(s[nt][0] - nm0);
            s[nt][1] = ex2(s[nt][1] - nm0);
            s[nt][2] = ex2(s[nt][2] - nm1);
            s[nt][3] = ex2(s[nt][3] - nm1);
            sum0 += s[nt][0] + s[nt][1];
            sum1 += s[nt][2] + s[nt][3];
        }
        sum0 += __shfl_xor_sync(0xffffffffu, sum0, 1);
        sum0 += __shfl_xor_sync(0xffffffffu, sum0, 2);
        sum1 += __shfl_xor_sync(0xffffffffu, sum1, 1);
        sum1 += __shfl_xor_sync(0xffffffffu, sum1, 2);
        l0 = l0 * c0 + sum0;
        l1 = l1 * c1 + sum1;

        #pragma unroll
        for (int dt = 0; dt < 8; dt++) {
            o[dt][0] *= c0;  o[dt][1] *= c0;
            o[dt][2] *= c1;  o[dt][3] *= c1;
        }

        // ---- O += P @ V ----
        #pragma unroll
        for (int kc = 0; kc < 8; kc++) {
            float x0, y0, x1, y1;
            pfrag(s[kc][0], s[kc][1], lane, x0, y0);
            pfrag(s[kc][2], s[kc][3], lane, x1, y1);
            uint32_t a[4];
            a[0] = f2tf32(x0);
            a[1] = f2tf32(x1);
            a[2] = f2tf32(y0);
            a[3] = f2tf32(y1);
            #pragma unroll
            for (int dt = 0; dt < 8; dt++) {
                float2 vv = *(const float2*)&Vt[dt*8 + g][kc*8 + 2*t];
                uint32_t bf[2];
                bf[0] = fbits(vv.x);
                bf[1] = fbits(vv.y);
                mma_tf32(o[dt], a, bf, o[dt]);
            }
        }
    }

    // ---- epilogue ----
    const float inv0 = 1.f / l0;
    const float inv1 = 1.f / l1;
    const int q0 = qBase + g;
    const int q1 = q0 + 8;
    float* orow0 = out + ((size_t)(b * S_ + q0)) * D_ + h * HD_;
    float* orow1 = out + ((size_t)(b * S_ + q1)) * D_ + h * HD_;
    #pragma unroll
    for (int dt = 0; dt < 8; dt++) {
        const int d = dt*8 + 2*t;
        float2 v0; v0.x = o[dt][0] * inv0; v0.y = o[dt][1] * inv0;
        float2 v1; v1.x = o[dt][2] * inv1; v1.y = o[dt][3] * inv1;
        *(float2*)&orow0[d] = v0;
        *(float2*)&orow1[d] = v1;
    }
}

// ---------------------------------------------------------------------------
extern "C" void kernel_launch(void* const* d_in, const int* in_sizes, int n_in,
                              void* d_out, int out_size)
{
    const float* v1   = (const float*)d_in[0];
    const float* mask = (const float*)d_in[1];
    const float* Wq   = (const float*)d_in[2];
    const float* bq   = (const float*)d_in[3];
    const float* Wk   = (const float*)d_in[4];
    const float* bk   = (const float*)d_in[5];
    const float* Wv   = (const float*)d_in[6];
    const float* bv   = (const float*)d_in[7];
    float* out = (float*)d_out;

    dim3 g1(H_, (B_ * S_) / 128, 3);
    qkv_mma_kernel<<<g1, 256>>>(v1, Wq, bq, Wk, bk, Wv, bv);

    dim3 g2(S_ / 64, B_ * H_);
    attn_mma_kernel<<<g2, 128>>>(mask, out);
}

// round 8
// speedup vs baseline: 1.4216x; 1.4216x over previous
#include <cuda_runtime.h>
#include <math.h>
#include <stdint.h>

#define B_  2
#define S_  2048
#define D_  768
#define H_  12
#define HD_ 64
#define LOG2E 1.44269504f

// Q/K/V scratch in [B,H,S,hd] layout (stored pre-rounded to tf32)
__device__ float g_q[B_*H_*S_*HD_];
__device__ float g_k[B_*H_*S_*HD_];
__device__ float g_v[B_*H_*S_*HD_];

// ---------------------------------------------------------------------------
// helpers
// ---------------------------------------------------------------------------
__device__ __forceinline__ uint32_t f2tf32(float x) {
    uint32_t r;
    asm("cvt.rna.tf32.f32 %0, %1;" : "=r"(r) : "f"(x));
    return r;
}
__device__ __forceinline__ uint32_t fbits(float x) { return __float_as_uint(x); }

__device__ __forceinline__ float ex2(float x) {
    float r;
    asm("ex2.approx.f32 %0, %1;" : "=f"(r) : "f"(x));
    return r;
}

__device__ __forceinline__ uint32_t s2u(const void* p) {
    uint32_t a;
    asm("{ .reg .u64 t; cvta.to.shared.u64 t, %1; cvt.u32.u64 %0, t; }"
        : "=r"(a) : "l"(p));
    return a;
}

__device__ __forceinline__ void cp16(uint32_t dst, const void* src) {
    asm volatile("cp.async.cg.shared.global [%0], [%1], 16;"
                 :: "r"(dst), "l"(src) : "memory");
}
__device__ __forceinline__ void cp_commit() {
    asm volatile("cp.async.commit_group;" ::: "memory");
}
template <int N>
__device__ __forceinline__ void cp_wait() {
    asm volatile("cp.async.wait_group %0;" :: "n"(N) : "memory");
}

__device__ __forceinline__ void mma_tf32(float (&d)[4], const uint32_t (&a)[4],
                                         const uint32_t (&b)[2], const float (&c)[4]) {
    asm volatile(
        "mma.sync.aligned.m16n8k8.row.col.f32.tf32.tf32.f32 "
        "{%0,%1,%2,%3}, {%4,%5,%6,%7}, {%8,%9}, {%10,%11,%12,%13};\n"
        : "=f"(d[0]), "=f"(d[1]), "=f"(d[2]), "=f"(d[3])
        : "r"(a[0]), "r"(a[1]), "r"(a[2]), "r"(a[3]),
          "r"(b[0]), "r"(b[1]),
          "f"(c[0]), "f"(c[1]), "f"(c[2]), "f"(c[3]));
}

// Route C-fragment col pair into A-fragment cols t, t+4 of same k-chunk.
__device__ __forceinline__ void pfrag(float pa, float pb, int lane, float& x, float& y) {
    const int t = lane & 3;
    const int base = lane & ~3;
    const int s1 = base | (t >> 1);
    const int s2 = base | ((t >> 1) + 2);
    float v0 = __shfl_sync(0xffffffffu, pa, s1);
    float v1 = __shfl_sync(0xffffffffu, pb, s1);
    float w0 = __shfl_sync(0xffffffffu, pa, s2);
    float w1 = __shfl_sync(0xffffffffu, pb, s2);
    x = (t & 1) ? v1 : v0;
    y = (t & 1) ? w1 : w0;
}

// ---------------------------------------------------------------------------
// QKV projection GEMM (tf32 mma.sync). Epilogue stores tf32-ROUNDED values
// so the attention kernel can copy tiles raw.
// ---------------------------------------------------------------------------
__global__ __launch_bounds__(256, 2)
void qkv_mma_kernel(const float* __restrict__ A,
                    const float* __restrict__ Wq, const float* __restrict__ bq,
                    const float* __restrict__ Wk, const float* __restrict__ bk,
                    const float* __restrict__ Wv, const float* __restrict__ bv)
{
    const float* W; const float* bias; float* out;
    switch (blockIdx.z) {
        case 0:  W = Wq; bias = bq; out = g_q; break;
        case 1:  W = Wk; bias = bk; out = g_k; break;
        default: W = Wv; bias = bv; out = g_v; break;
    }

    __shared__ float As[128][36];
    __shared__ float Bs[32][72];

    const int tid  = threadIdx.x;
    const int w    = tid >> 5;
    const int lane = tid & 31;
    const int g    = lane >> 2;
    const int t    = lane & 3;
    const int wm   = w & 3;
    const int wn   = w >> 2;
    const int rowBase = blockIdx.y * 128;
    const int h       = blockIdx.x;
    const int colBase = h * 64;

    float acc[2][4][4];
    #pragma unroll
    for (int mt = 0; mt < 2; mt++)
        #pragma unroll
        for (int nt = 0; nt < 4; nt++)
            #pragma unroll
            for (int i = 0; i < 4; i++) acc[mt][nt][i] = 0.f;

    const int ar = tid >> 3, ac = (tid & 7) * 4;
    const int br = tid >> 4, bc = (tid & 15) * 4;

    for (int k0 = 0; k0 < D_; k0 += 32) {
        __syncthreads();
        #pragma unroll
        for (int p = 0; p < 4; p++) {
            float4 v = *(const float4*)&A[(size_t)(rowBase + ar + p*32) * D_ + k0 + ac];
            float* d = &As[ar + p*32][ac];
            d[0] = __uint_as_float(f2tf32(v.x));
            d[1] = __uint_as_float(f2tf32(v.y));
            d[2] = __uint_as_float(f2tf32(v.z));
            d[3] = __uint_as_float(f2tf32(v.w));
        }
        #pragma unroll
        for (int p = 0; p < 2; p++) {
            float4 v = *(const float4*)&W[(size_t)(k0 + br + p*16) * D_ + colBase + bc];
            float* d = &Bs[br + p*16][bc];
            d[0] = __uint_as_float(f2tf32(v.x));
            d[1] = __uint_as_float(f2tf32(v.y));
            d[2] = __uint_as_float(f2tf32(v.z));
            d[3] = __uint_as_float(f2tf32(v.w));
        }
        __syncthreads();

        #pragma unroll
        for (int kc = 0; kc < 4; kc++) {
            uint32_t af[2][4];
            #pragma unroll
            for (int mt = 0; mt < 2; mt++) {
                const int r = wm*32 + mt*16;
                af[mt][0] = fbits(As[r + g    ][kc*8 + t    ]);
                af[mt][1] = fbits(As[r + g + 8][kc*8 + t    ]);
                af[mt][2] = fbits(As[r + g    ][kc*8 + t + 4]);
                af[mt][3] = fbits(As[r + g + 8][kc*8 + t + 4]);
            }
            #pragma unroll
            for (int nt = 0; nt < 4; nt++) {
                uint32_t bf[2];
                bf[0] = fbits(Bs[kc*8 + t    ][wn*32 + nt*8 + g]);
                bf[1] = fbits(Bs[kc*8 + t + 4][wn*32 + nt*8 + g]);
                mma_tf32(acc[0][nt], af[0], bf, acc[0][nt]);
                mma_tf32(acc[1][nt], af[1], bf, acc[1][nt]);
            }
        }
    }

    #pragma unroll
    for (int mt = 0; mt < 2; mt++) {
        #pragma unroll
        for (int half = 0; half < 2; half++) {
            const int row = rowBase + wm*32 + mt*16 + g + half*8;
            const int b   = row >> 11;
            const int s   = row & (S_ - 1);
            float* orow = out + ((size_t)(b*H_ + h) * S_ + s) * HD_;
            #pragma unroll
            for (int nt = 0; nt < 4; nt++) {
                const int d = wn*32 + nt*8 + 2*t;
                float2 v;
                v.x = __uint_as_float(f2tf32(acc[mt][nt][half*2 + 0] + bias[colBase + d]));
                v.y = __uint_as_float(f2tf32(acc[mt][nt][half*2 + 1] + bias[colBase + d + 1]));
                *(float2*)&orow[d] = v;
            }
        }
    }
}

// ---------------------------------------------------------------------------
// Flash attention (tf32 mma.sync) with cp.async double-buffered K/V tiles.
// block = 128 (4 warps), 64 queries/CTA, 3 CTAs/SM, grid (S/64=32, B*H=24).
// Smem (dynamic, 72.2KB): K[2][64][68], V[2][64][72] (natural row-major,
// pre-rounded tf32), mask[2][64].
// Fragment banks: QK-B bank = 4g+t (stride 68), PV-B bank = 8t+g (stride 72),
// both conflict-free; PV reads natural V rows (no transpose).
// ---------------------------------------------------------------------------
#define KSTR 68
#define VSTR 72
#define KTILE_F (64*KSTR)          // floats per K buffer
#define VTILE_F (64*VSTR)
#define OFF_V   (2*KTILE_F)        // float offset of V buffers
#define OFF_M   (2*KTILE_F + 2*VTILE_F)
#define ATTN_SMEM_BYTES ((OFF_M + 2*64) * 4)

__global__ __launch_bounds__(128, 3)
void attn_mma_kernel(const float* __restrict__ mask, float* __restrict__ out)
{
    extern __shared__ float smem[];

    const int tid  = threadIdx.x;
    const int w    = tid >> 5;
    const int lane = tid & 31;
    const int g    = lane >> 2;
    const int t    = lane & 3;

    const int bh = blockIdx.y;
    const int b  = bh / H_;
    const int h  = bh % H_;
    const int qBase = blockIdx.x * 64 + w * 16;

    const float* Qg = g_q + (size_t)bh * S_ * HD_;
    const float* Kg = g_k + (size_t)bh * S_ * HD_;
    const float* Vg = g_v + (size_t)bh * S_ * HD_;
    const float* mrow = mask + (size_t)b * S_;

    const uint32_t smem_u = s2u(smem);
    const int crow = tid >> 4;        // 0..7   (copy row group)
    const int ccol = tid & 15;        // 16B chunk within row

    // prefetch one tile (K, V, mask) into buffer bb
    auto prefetch = [&](int tile, int bb) {
        const float* Ksrc = Kg + (size_t)tile * 64 * HD_;
        const float* Vsrc = Vg + (size_t)tile * 64 * HD_;
        const uint32_t kdst = smem_u + (uint32_t)bb * (KTILE_F*4);
        const uint32_t vdst = smem_u + (uint32_t)(OFF_V + bb*VTILE_F) * 4;
        #pragma unroll
        for (int p = 0; p < 8; p++) {
            const int row = crow + p*8;
            cp16(kdst + row*(KSTR*4) + ccol*16, Ksrc + row*HD_ + ccol*4);
            cp16(vdst + row*(VSTR*4) + ccol*16, Vsrc + row*HD_ + ccol*4);
        }
        if (tid < 16)
            cp16(smem_u + (uint32_t)(OFF_M + bb*64 + tid*4) * 4, mrow + tile*64 + tid*4);
        cp_commit();
    };

    // ---- Q fragments (g_q already tf32-rounded; rescale + round once) ----
    const float qscale = 0.125f * LOG2E;
    uint32_t qf[8][4];
    {
        const float* q0 = Qg + (size_t)(qBase + g)     * HD_;
        const float* q1 = Qg + (size_t)(qBase + g + 8) * HD_;
        #pragma unroll
        for (int kc = 0; kc < 8; kc++) {
            qf[kc][0] = f2tf32(q0[8*kc + t    ] * qscale);
            qf[kc][1] = f2tf32(q1[8*kc + t    ] * qscale);
            qf[kc][2] = f2tf32(q0[8*kc + t + 4] * qscale);
            qf[kc][3] = f2tf32(q1[8*kc + t + 4] * qscale);
        }
    }

    float o[8][4];
    #pragma unroll
    for (int dt = 0; dt < 8; dt++)
        #pragma unroll
        for (int i = 0; i < 4; i++) o[dt][i] = 0.f;

    float m0 = -INFINITY, m1 = -INFINITY, l0 = 0.f, l1 = 0.f;

    prefetch(0, 0);

    #pragma unroll 1
    for (int tile = 0; tile < 32; ++tile) {
        const int cur = tile & 1;
        if (tile < 31) prefetch(tile + 1, cur ^ 1);
        if (tile < 31) cp_wait<1>(); else cp_wait<0>();
        __syncthreads();

        const float* Ks = smem + cur * KTILE_F;          // [64][68]
        const float* Vs = smem + OFF_V + cur * VTILE_F;  // [64][72]
        const float* Ms = smem + OFF_M + cur * 64;

        // ---- S = (Q*scale) @ K^T + mask (log2 domain) ----
        float s[8][4];
        #pragma unroll
        for (int nt = 0; nt < 8; nt++) {
            #pragma unroll
            for (int i = 0; i < 4; i++) s[nt][i] = 0.f;
            const float* krow = Ks + (nt*8 + g) * KSTR;
            #pragma unroll
            for (int kc = 0; kc < 8; kc++) {
                uint32_t bf[2];
                bf[0] = fbits(krow[kc*8 + t    ]);
                bf[1] = fbits(krow[kc*8 + t + 4]);
                mma_tf32(s[nt], qf[kc], bf, s[nt]);
            }
            const float mk0 = Ms[nt*8 + 2*t]     * LOG2E;
            const float mk1 = Ms[nt*8 + 2*t + 1] * LOG2E;
            s[nt][0] += mk0;  s[nt][1] += mk1;
            s[nt][2] += mk0;  s[nt][3] += mk1;
        }

        // ---- online softmax ----
        float mx0 = -INFINITY, mx1 = -INFINITY;
        #pragma unroll
        for (int nt = 0; nt < 8; nt++) {
            mx0 = fmaxf(mx0, fmaxf(s[nt][0], s[nt][1]));
            mx1 = fmaxf(mx1, fmaxf(s[nt][2], s[nt][3]));
        }
        mx0 = fmaxf(mx0, __shfl_xor_sync(0xffffffffu, mx0, 1));
        mx0 = fmaxf(mx0, __shfl_xor_sync(0xffffffffu, mx0, 2));
        mx1 = fmaxf(mx1, __shfl_xor_sync(0xffffffffu, mx1, 1));
        mx1 = fmaxf(mx1, __shfl_xor_sync(0xffffffffu, mx1, 2));

        const float nm0 = fmaxf(m0, mx0);
        const float nm1 = fmaxf(m1, mx1);
        const float c0 = ex2(m0 - nm0);
        const float c1 = ex2(m1 - nm1);
        m0 = nm0; m1 = nm1;

        float sum0 = 0.f, sum1 = 0.f;
        #pragma unroll
        for (int nt = 0; nt < 8; nt++) {
            s[nt][0] = ex2(s[nt][0] - nm0);
            s[nt][1] = ex2(s[nt][1] - nm0);
            s[nt][2] = ex2(s[nt][2] - nm1);
            s[nt][3] = ex2(s[nt][3] - nm1);
            sum0 += s[nt][0] + s[nt][1];
            sum1 += s[nt][2] + s[nt][3];
        }
        sum0 += __shfl_xor_sync(0xffffffffu, sum0, 1);
        sum0 += __shfl_xor_sync(0xffffffffu, sum0, 2);
        sum1 += __shfl_xor_sync(0xffffffffu, sum1, 1);
        sum1 += __shfl_xor_sync(0xffffffffu, sum1, 2);
        l0 = l0 * c0 + sum0;
        l1 = l1 * c1 + sum1;

        #pragma unroll
        for (int dt = 0; dt < 8; dt++) {
            o[dt][0] *= c0;  o[dt][1] *= c0;
            o[dt][2] *= c1;  o[dt][3] *= c1;
        }

        // ---- O += P @ V (B read from natural V rows: B[n=g][k=t] = V[k][n]) ----
        #pragma unroll
        for (int kc = 0; kc < 8; kc++) {
            float x0, y0, x1, y1;
            pfrag(s[kc][0], s[kc][1], lane, x0, y0);
            pfrag(s[kc][2], s[kc][3], lane, x1, y1);
            uint32_t a[4];
            a[0] = f2tf32(x0);
            a[1] = f2tf32(x1);
            a[2] = f2tf32(y0);
            a[3] = f2tf32(y1);
            const float* v0 = Vs + (kc*8 + t    ) * VSTR;
            const float* v1 = Vs + (kc*8 + t + 4) * VSTR;
            #pragma unroll
            for (int dt = 0; dt < 8; dt++) {
                uint32_t bf[2];
                bf[0] = fbits(v0[dt*8 + g]);
                bf[1] = fbits(v1[dt*8 + g]);
                mma_tf32(o[dt], a, bf, o[dt]);
            }
        }
        __syncthreads();   // all reads done before next prefetch overwrites buffer
    }

    // ---- epilogue ----
    const float inv0 = 1.f / l0;
    const float inv1 = 1.f / l1;
    const int q0 = qBase + g;
    const int q1 = q0 + 8;
    float* orow0 = out + ((size_t)(b * S_ + q0)) * D_ + h * HD_;
    float* orow1 = out + ((size_t)(b * S_ + q1)) * D_ + h * HD_;
    #pragma unroll
    for (int dt = 0; dt < 8; dt++) {
        const int d = dt*8 + 2*t;
        float2 v0; v0.x = o[dt][0] * inv0; v0.y = o[dt][1] * inv0;
        float2 v1; v1.x = o[dt][2] * inv1; v1.y = o[dt][3] * inv1;
        *(float2*)&orow0[d] = v0;
        *(float2*)&orow1[d] = v1;
    }
}

// ---------------------------------------------------------------------------
extern "C" void kernel_launch(void* const* d_in, const int* in_sizes, int n_in,
                              void* d_out, int out_size)
{
    const float* v1   = (const float*)d_in[0];
    const float* mask = (const float*)d_in[1];
    const float* Wq   = (const float*)d_in[2];
    const float* bq   = (const float*)d_in[3];
    const float* Wk   = (const float*)d_in[4];
    const float* bk   = (const float*)d_in[5];
    const float* Wv   = (const float*)d_in[6];
    const float* bv   = (const float*)d_in[7];
    float* out = (float*)d_out;

    cudaFuncSetAttribute(attn_mma_kernel,
                         cudaFuncAttributeMaxDynamicSharedMemorySize,
                         ATTN_SMEM_BYTES);

    dim3 g1(H_, (B_ * S_) / 128, 3);
    qkv_mma_kernel<<<g1, 256>>>(v1, Wq, bq, Wk, bk, Wv, bv);

    dim3 g2(S_ / 64, B_ * H_);
    attn_mma_kernel<<<g2, 128, ATTN_SMEM_BYTES>>>(mask, out);
}